// round 3
// baseline (speedup 1.0000x reference)
#include <cuda_runtime.h>
#include <cstdint>

#define S_ROWS 50000
#define P_ROWS 10000
#define EMBED_DIM 64
#define CHUNKS 16           // 64 floats = 16 float4
#define CAP 3200000         // edge capacity per list

// ---------------- static device scratch (no cudaMalloc allowed) ----------------
__device__ int2 g_ent_a_r[CAP];    // list A sorted by row  : (col, val_bits)
__device__ int2 g_ent_a_c[CAP];    // list A sorted by col  : (row, val_bits)
__device__ int2 g_ent_ia_r[CAP];   // list IA sorted by row
__device__ int2 g_ent_ia_c[CAP];   // list IA sorted by col

__device__ int g_cnt_a_r[S_ROWS];
__device__ int g_cnt_a_c[P_ROWS];
__device__ int g_cnt_ia_r[S_ROWS];
__device__ int g_cnt_ia_c[P_ROWS];

__device__ int g_ptr_a_r[S_ROWS + 1];
__device__ int g_ptr_a_c[P_ROWS + 1];
__device__ int g_ptr_ia_r[S_ROWS + 1];
__device__ int g_ptr_ia_c[P_ROWS + 1];

__device__ int g_cur_a_r[S_ROWS];
__device__ int g_cur_a_c[P_ROWS];
__device__ int g_cur_ia_r[S_ROWS];
__device__ int g_cur_ia_c[P_ROWS];

// ---------------- kernels ----------------

__global__ void zero_counts_kernel() {
    int i = blockIdx.x * blockDim.x + threadIdx.x;
    if (i < S_ROWS) { g_cnt_a_r[i] = 0; g_cnt_ia_r[i] = 0; }
    if (i < P_ROWS) { g_cnt_a_c[i] = 0; g_cnt_ia_c[i] = 0; }
}

template <int LIST>
__global__ void hist_kernel(const int* __restrict__ rows,
                            const int* __restrict__ cols, int nnz) {
    int e = blockIdx.x * blockDim.x + threadIdx.x;
    if (e >= nnz) return;
    if (LIST == 0) {
        atomicAdd(&g_cnt_a_r[rows[e]], 1);
        atomicAdd(&g_cnt_a_c[cols[e]], 1);
    } else {
        atomicAdd(&g_cnt_ia_r[rows[e]], 1);
        atomicAdd(&g_cnt_ia_c[cols[e]], 1);
    }
}

// One block per array; exclusive scan, writes ptr[0..n] and cur[0..n-1].
__global__ void scan_kernel() {
    const int* cnt; int* ptr; int* cur; int n;
    switch (blockIdx.x) {
        case 0:  cnt = g_cnt_a_r;  ptr = g_ptr_a_r;  cur = g_cur_a_r;  n = S_ROWS; break;
        case 1:  cnt = g_cnt_a_c;  ptr = g_ptr_a_c;  cur = g_cur_a_c;  n = P_ROWS; break;
        case 2:  cnt = g_cnt_ia_r; ptr = g_ptr_ia_r; cur = g_cur_ia_r; n = S_ROWS; break;
        default: cnt = g_cnt_ia_c; ptr = g_ptr_ia_c; cur = g_cur_ia_c; n = P_ROWS; break;
    }

    const int tid = threadIdx.x;
    const int lane = tid & 31;
    const int wid = tid >> 5;
    __shared__ int wsum[32];
    __shared__ int s_total;

    int carry = 0;
    for (int base = 0; base < n; base += 1024) {
        int i = base + tid;
        int x = (i < n) ? cnt[i] : 0;

        // warp inclusive scan
        int v = x;
        #pragma unroll
        for (int o = 1; o < 32; o <<= 1) {
            int y = __shfl_up_sync(0xffffffffu, v, o);
            if (lane >= o) v += y;
        }
        if (lane == 31) wsum[wid] = v;
        __syncthreads();
        if (wid == 0) {
            int w = wsum[lane];
            #pragma unroll
            for (int o = 1; o < 32; o <<= 1) {
                int y = __shfl_up_sync(0xffffffffu, w, o);
                if (lane >= o) w += y;
            }
            wsum[lane] = w;
            if (lane == 31) s_total = w;
        }
        __syncthreads();
        int prefix = (wid > 0) ? wsum[wid - 1] : 0;
        int excl = carry + prefix + (v - x);
        if (i < n) { ptr[i] = excl; cur[i] = excl; }
        carry += s_total;
        __syncthreads();  // protect wsum before next tile
    }
    if (tid == 0) ptr[n] = carry;
}

template <int LIST>
__global__ void scatter_kernel(const int* __restrict__ rows,
                               const int* __restrict__ cols,
                               const float* __restrict__ vals, int nnz) {
    int e = blockIdx.x * blockDim.x + threadIdx.x;
    if (e >= nnz) return;
    int r = rows[e], cl = cols[e];
    int vb = __float_as_int(vals[e]);
    if (LIST == 0) {
        int pr = atomicAdd(&g_cur_a_r[r], 1);
        g_ent_a_r[pr] = make_int2(cl, vb);
        int pc = atomicAdd(&g_cur_a_c[cl], 1);
        g_ent_a_c[pc] = make_int2(r, vb);
    } else {
        int pr = atomicAdd(&g_cur_ia_r[r], 1);
        g_ent_ia_r[pr] = make_int2(cl, vb);
        int pc = atomicAdd(&g_cur_ia_c[cl], 1);
        g_ent_ia_c[pc] = make_int2(r, vb);
    }
}

// ID: 0 = A by row, 1 = A by col, 2 = IA by row, 3 = IA by col
// 16 threads per output row; thread c owns float4 chunk c. Edges are read
// coalesced 16-at-a-time and broadcast within the 16-lane group via shfl.
template <int ID>
__global__ void reduce_kernel(const float4* __restrict__ src,
                              float4* __restrict__ out, int nrows) {
    int gt = blockIdx.x * blockDim.x + threadIdx.x;
    int row = gt >> 4;
    int c = gt & 15;
    if (row >= nrows) return;

    const int2* ent; const int* ptr;
    if (ID == 0)      { ent = g_ent_a_r;  ptr = g_ptr_a_r;  }
    else if (ID == 1) { ent = g_ent_a_c;  ptr = g_ptr_a_c;  }
    else if (ID == 2) { ent = g_ent_ia_r; ptr = g_ptr_ia_r; }
    else              { ent = g_ent_ia_c; ptr = g_ptr_ia_c; }

    int start = ptr[row];
    int end = ptr[row + 1];

    float4 acc = make_float4(0.f, 0.f, 0.f, 0.f);
    for (int base = start; base < end; base += 16) {
        int e = base + c;
        int2 pk = (e < end) ? __ldg(&ent[e]) : make_int2(0, 0);
        int cnt = min(16, end - base);
        for (int j = 0; j < cnt; j++) {
            int  s = __shfl_sync(0xffffffffu, pk.x, j, 16);
            float v = __int_as_float(__shfl_sync(0xffffffffu, pk.y, j, 16));
            float4 sv = __ldg(&src[(unsigned)s * CHUNKS + c]);
            acc.x = fmaf(v, sv.x, acc.x);
            acc.y = fmaf(v, sv.y, acc.y);
            acc.z = fmaf(v, sv.z, acc.z);
            acc.w = fmaf(v, sv.w, acc.w);
        }
    }
    out[(unsigned)row * CHUNKS + c] = acc;
}

// ---------------- launch ----------------

extern "C" void kernel_launch(void* const* d_in, const int* in_sizes, int n_in,
                              void* d_out, int out_size) {
    const float* student_embeds = (const float*)d_in[0];
    const float* problem_embeds = (const float*)d_in[1];
    const int*   a_rows  = (const int*)d_in[2];
    const int*   a_cols  = (const int*)d_in[3];
    const float* a_vals  = (const float*)d_in[4];
    const int*   ia_rows = (const int*)d_in[5];
    const int*   ia_cols = (const int*)d_in[6];
    const float* ia_vals = (const float*)d_in[7];

    float* out = (float*)d_out;
    const int nnz = in_sizes[2];

    float* out_student_c  = out;
    float* out_student_ic = out + S_ROWS * EMBED_DIM;
    float* out_problem_c  = out + 2 * S_ROWS * EMBED_DIM;
    float* out_problem_ic = out + 2 * S_ROWS * EMBED_DIM + P_ROWS * EMBED_DIM;

    const int T = 256;
    int eb = (nnz + T - 1) / T;

    // 1) zero histogram counters
    zero_counts_kernel<<<(S_ROWS + T - 1) / T, T>>>();

    // 2) histograms for both edge lists
    hist_kernel<0><<<eb, T>>>(a_rows, a_cols, nnz);
    hist_kernel<1><<<eb, T>>>(ia_rows, ia_cols, nnz);

    // 3) exclusive scans (4 arrays, one block each)
    scan_kernel<<<4, 1024>>>();

    // 4) scatter edges into CSR/CSC buckets
    scatter_kernel<0><<<eb, T>>>(a_rows, a_cols, a_vals, nnz);
    scatter_kernel<1><<<eb, T>>>(ia_rows, ia_cols, ia_vals, nnz);

    // 5) register-accumulated reductions (no atomics, single store per row)
    int sb = (S_ROWS * CHUNKS) / T;   // 3125, exact
    int pb = (P_ROWS * CHUNKS) / T;   // 625, exact
    reduce_kernel<0><<<sb, T>>>((const float4*)problem_embeds,
                                (float4*)out_student_c, S_ROWS);
    reduce_kernel<2><<<sb, T>>>((const float4*)problem_embeds,
                                (float4*)out_student_ic, S_ROWS);
    reduce_kernel<1><<<pb, T>>>((const float4*)student_embeds,
                                (float4*)out_problem_c, P_ROWS);
    reduce_kernel<3><<<pb, T>>>((const float4*)student_embeds,
                                (float4*)out_problem_ic, P_ROWS);
}

// round 4
// speedup vs baseline: 1.1554x; 1.1554x over previous
#include <cuda_runtime.h>
#include <cstdint>

#define S_ROWS 50000
#define P_ROWS 10000
#define EMBED_DIM 64
#define CHUNKS 16           // 64 floats = 16 float4
#define CAP 3200000         // edges per list

// scan tiling
#define SCHUNK 2048
#define S_NCHUNK 25         // ceil(50000/2048)
#define P_NCHUNK 5          // ceil(10000/2048)
#define TOT_CHUNKS 60       // 25 + 5 + 25 + 5

// reduce block counts (256 threads, 16 rows/block)
#define SB 3125             // 50000*16/256
#define PB 625              // 10000*16/256

// ---------------- static device scratch ----------------
__device__ int2 g_ent_a_r[CAP];
__device__ int2 g_ent_a_c[CAP];
__device__ int2 g_ent_ia_r[CAP];
__device__ int2 g_ent_ia_c[CAP];

__device__ int g_rank_a_r[CAP];
__device__ int g_rank_a_c[CAP];
__device__ int g_rank_ia_r[CAP];
__device__ int g_rank_ia_c[CAP];

__device__ int g_cnt_a_r[S_ROWS];
__device__ int g_cnt_a_c[P_ROWS];
__device__ int g_cnt_ia_r[S_ROWS];
__device__ int g_cnt_ia_c[P_ROWS];

__device__ int g_ptr_a_r[S_ROWS + 1];
__device__ int g_ptr_a_c[P_ROWS + 1];
__device__ int g_ptr_ia_r[S_ROWS + 1];
__device__ int g_ptr_ia_c[P_ROWS + 1];

__device__ int g_part[TOT_CHUNKS];

// map scan block id -> (cnt, ptr, n, chunk)
__device__ __forceinline__ void scan_map(int b, const int*& cnt, int*& ptr,
                                         int& n, int& chunk) {
    if (b < S_NCHUNK)                    { cnt = g_cnt_a_r;  ptr = g_ptr_a_r;  n = S_ROWS; chunk = b; }
    else if (b < S_NCHUNK + P_NCHUNK)    { cnt = g_cnt_a_c;  ptr = g_ptr_a_c;  n = P_ROWS; chunk = b - S_NCHUNK; }
    else if (b < 2*S_NCHUNK + P_NCHUNK)  { cnt = g_cnt_ia_r; ptr = g_ptr_ia_r; n = S_ROWS; chunk = b - S_NCHUNK - P_NCHUNK; }
    else                                 { cnt = g_cnt_ia_c; ptr = g_ptr_ia_c; n = P_ROWS; chunk = b - 2*S_NCHUNK - P_NCHUNK; }
}

// ---------------- kernels ----------------

__global__ void zero_counts_kernel() {
    int i = blockIdx.x * blockDim.x + threadIdx.x;
    if (i < S_ROWS) { g_cnt_a_r[i] = 0; g_cnt_ia_r[i] = 0; }
    if (i < P_ROWS) { g_cnt_a_c[i] = 0; g_cnt_ia_c[i] = 0; }
}

// histogram + per-edge rank capture, both lists in one launch
__global__ void hist_all_kernel(const int* __restrict__ a_rows,
                                const int* __restrict__ a_cols,
                                const int* __restrict__ ia_rows,
                                const int* __restrict__ ia_cols,
                                int nnz, int eb) {
    int b = blockIdx.x;
    if (b < eb) {
        int e = b * blockDim.x + threadIdx.x;
        if (e < nnz) {
            int r = __ldcs(&a_rows[e]);
            int c = __ldcs(&a_cols[e]);
            g_rank_a_r[e] = atomicAdd(&g_cnt_a_r[r], 1);
            g_rank_a_c[e] = atomicAdd(&g_cnt_a_c[c], 1);
        }
    } else {
        int e = (b - eb) * blockDim.x + threadIdx.x;
        if (e < nnz) {
            int r = __ldcs(&ia_rows[e]);
            int c = __ldcs(&ia_cols[e]);
            g_rank_ia_r[e] = atomicAdd(&g_cnt_ia_r[r], 1);
            g_rank_ia_c[e] = atomicAdd(&g_cnt_ia_c[c], 1);
        }
    }
}

// scan stage 1: per-chunk sums
__global__ void scan_stage1() {
    const int* cnt; int* ptr; int n, chunk;
    scan_map(blockIdx.x, cnt, ptr, n, chunk);
    int tid = threadIdx.x;
    int base = chunk * SCHUNK + tid * 8;
    int s = 0;
    #pragma unroll
    for (int i = 0; i < 8; i++) {
        int idx = base + i;
        if (idx < n) s += cnt[idx];
    }
    // warp reduce
    #pragma unroll
    for (int o = 16; o > 0; o >>= 1) s += __shfl_down_sync(0xffffffffu, s, o);
    __shared__ int wsum[8];
    if ((tid & 31) == 0) wsum[tid >> 5] = s;
    __syncthreads();
    if (tid == 0) {
        int t = 0;
        #pragma unroll
        for (int w = 0; w < 8; w++) t += wsum[w];
        g_part[blockIdx.x] = t;
    }
}

// scan stage 2: segmented exclusive scan of 60 partials (single thread; trivial)
__global__ void scan_mid() {
    if (threadIdx.x != 0) return;
    int c = 0;
    for (int i = 0; i < S_NCHUNK; i++) { int x = g_part[i]; g_part[i] = c; c += x; }
    g_ptr_a_r[S_ROWS] = c;
    c = 0;
    for (int i = S_NCHUNK; i < S_NCHUNK + P_NCHUNK; i++) { int x = g_part[i]; g_part[i] = c; c += x; }
    g_ptr_a_c[P_ROWS] = c;
    c = 0;
    for (int i = S_NCHUNK + P_NCHUNK; i < 2*S_NCHUNK + P_NCHUNK; i++) { int x = g_part[i]; g_part[i] = c; c += x; }
    g_ptr_ia_r[S_ROWS] = c;
    c = 0;
    for (int i = 2*S_NCHUNK + P_NCHUNK; i < TOT_CHUNKS; i++) { int x = g_part[i]; g_part[i] = c; c += x; }
    g_ptr_ia_c[P_ROWS] = c;
}

// scan stage 3: in-chunk exclusive scan + chunk offset -> ptr
__global__ void scan_final() {
    const int* cnt; int* ptr; int n, chunk;
    scan_map(blockIdx.x, cnt, ptr, n, chunk);
    int tid = threadIdx.x;
    int lane = tid & 31, wid = tid >> 5;
    int base = chunk * SCHUNK + tid * 8;

    int x[8];
    int tsum = 0;
    #pragma unroll
    for (int i = 0; i < 8; i++) {
        int idx = base + i;
        x[i] = (idx < n) ? cnt[idx] : 0;
        tsum += x[i];
    }
    // warp inclusive scan of thread sums
    int v = tsum;
    #pragma unroll
    for (int o = 1; o < 32; o <<= 1) {
        int y = __shfl_up_sync(0xffffffffu, v, o);
        if (lane >= o) v += y;
    }
    __shared__ int wsum[8];
    __shared__ int wpre[8];
    if (lane == 31) wsum[wid] = v;
    __syncthreads();
    if (tid == 0) {
        int c = 0;
        #pragma unroll
        for (int w = 0; w < 8; w++) { wpre[w] = c; c += wsum[w]; }
    }
    __syncthreads();

    int run = g_part[blockIdx.x] + wpre[wid] + (v - tsum);
    #pragma unroll
    for (int i = 0; i < 8; i++) {
        int idx = base + i;
        if (idx < n) ptr[idx] = run;
        run += x[i];
    }
}

// scatter: atomic-free, pos = ptr[key] + rank[e]; both lists in one launch
__global__ void scatter_all_kernel(const int* __restrict__ a_rows,
                                   const int* __restrict__ a_cols,
                                   const float* __restrict__ a_vals,
                                   const int* __restrict__ ia_rows,
                                   const int* __restrict__ ia_cols,
                                   const float* __restrict__ ia_vals,
                                   int nnz, int eb) {
    int b = blockIdx.x;
    if (b < eb) {
        int e = b * blockDim.x + threadIdx.x;
        if (e < nnz) {
            int r = __ldcs(&a_rows[e]);
            int c = __ldcs(&a_cols[e]);
            int vb = __float_as_int(__ldcs(&a_vals[e]));
            g_ent_a_r[g_ptr_a_r[r] + __ldcs(&g_rank_a_r[e])] = make_int2(c, vb);
            g_ent_a_c[g_ptr_a_c[c] + __ldcs(&g_rank_a_c[e])] = make_int2(r, vb);
        }
    } else {
        int e = (b - eb) * blockDim.x + threadIdx.x;
        if (e < nnz) {
            int r = __ldcs(&ia_rows[e]);
            int c = __ldcs(&ia_cols[e]);
            int vb = __float_as_int(__ldcs(&ia_vals[e]));
            g_ent_ia_r[g_ptr_ia_r[r] + __ldcs(&g_rank_ia_r[e])] = make_int2(c, vb);
            g_ent_ia_c[g_ptr_ia_c[c] + __ldcs(&g_rank_ia_c[e])] = make_int2(r, vb);
        }
    }
}

// fused reduce: 16 threads per output row, register accumulation, one store.
// Heavy segments (problem outputs, avg 320 edges/row) dispatched FIRST.
__global__ void reduce_all_kernel(const float4* __restrict__ s_emb,
                                  const float4* __restrict__ p_emb,
                                  float4* __restrict__ out_sc,
                                  float4* __restrict__ out_sic,
                                  float4* __restrict__ out_pc,
                                  float4* __restrict__ out_pic) {
    int b = blockIdx.x;
    const int2* ent; const int* ptr; const float4* src; float4* out;
    if (b < PB)               { ent = g_ent_a_c;  ptr = g_ptr_a_c;  src = s_emb; out = out_pc;  }
    else if (b < 2*PB)        { ent = g_ent_ia_c; ptr = g_ptr_ia_c; src = s_emb; out = out_pic; b -= PB; }
    else if (b < 2*PB + SB)   { ent = g_ent_a_r;  ptr = g_ptr_a_r;  src = p_emb; out = out_sc;  b -= 2*PB; }
    else                      { ent = g_ent_ia_r; ptr = g_ptr_ia_r; src = p_emb; out = out_sic; b -= 2*PB + SB; }

    int gt = b * blockDim.x + threadIdx.x;
    int row = gt >> 4;
    int c = gt & 15;

    int start = ptr[row];
    int end = ptr[row + 1];

    float4 acc = make_float4(0.f, 0.f, 0.f, 0.f);
    for (int base = start; base < end; base += 16) {
        int e = base + c;
        int2 pk = (e < end) ? __ldcs(&ent[e]) : make_int2(0, 0);
        int cnt = min(16, end - base);
        for (int j = 0; j < cnt; j++) {
            int   s = __shfl_sync(0xffffffffu, pk.x, j, 16);
            float v = __int_as_float(__shfl_sync(0xffffffffu, pk.y, j, 16));
            float4 sv = __ldg(&src[(unsigned)s * CHUNKS + c]);
            acc.x = fmaf(v, sv.x, acc.x);
            acc.y = fmaf(v, sv.y, acc.y);
            acc.z = fmaf(v, sv.z, acc.z);
            acc.w = fmaf(v, sv.w, acc.w);
        }
    }
    out[(unsigned)row * CHUNKS + c] = acc;
}

// ---------------- launch ----------------

extern "C" void kernel_launch(void* const* d_in, const int* in_sizes, int n_in,
                              void* d_out, int out_size) {
    const float* student_embeds = (const float*)d_in[0];
    const float* problem_embeds = (const float*)d_in[1];
    const int*   a_rows  = (const int*)d_in[2];
    const int*   a_cols  = (const int*)d_in[3];
    const float* a_vals  = (const float*)d_in[4];
    const int*   ia_rows = (const int*)d_in[5];
    const int*   ia_cols = (const int*)d_in[6];
    const float* ia_vals = (const float*)d_in[7];

    float* out = (float*)d_out;
    const int nnz = in_sizes[2];

    float* out_student_c  = out;
    float* out_student_ic = out + S_ROWS * EMBED_DIM;
    float* out_problem_c  = out + 2 * S_ROWS * EMBED_DIM;
    float* out_problem_ic = out + 2 * S_ROWS * EMBED_DIM + P_ROWS * EMBED_DIM;

    const int T = 256;
    int eb = (nnz + T - 1) / T;

    zero_counts_kernel<<<(S_ROWS + T - 1) / T, T>>>();
    hist_all_kernel<<<2 * eb, T>>>(a_rows, a_cols, ia_rows, ia_cols, nnz, eb);
    scan_stage1<<<TOT_CHUNKS, T>>>();
    scan_mid<<<1, 32>>>();
    scan_final<<<TOT_CHUNKS, T>>>();
    scatter_all_kernel<<<2 * eb, T>>>(a_rows, a_cols, a_vals,
                                      ia_rows, ia_cols, ia_vals, nnz, eb);
    reduce_all_kernel<<<2 * SB + 2 * PB, T>>>(
        (const float4*)student_embeds, (const float4*)problem_embeds,
        (float4*)out_student_c, (float4*)out_student_ic,
        (float4*)out_problem_c, (float4*)out_problem_ic);
}